// round 15
// baseline (speedup 1.0000x reference)
#include <cuda_runtime.h>
#include <cuda_fp16.h>
#include <cstdint>

#define DINLINE __device__ __forceinline__

// ---------------- problem constants ----------------
constexpr int M_TOTAL = 8192;
constexpr int N_TOTAL = 16384;
constexpr int K_TOTAL = 4096;

// ---------------- GEMM tiling ----------------
constexpr int BM = 128;
constexpr int BN = 128;
constexpr int BK = 64;                    // fp16 elems per chunk row = 128 B (SW128 atom)
constexpr int NCHUNK = K_TOTAL / BK;      // 64
constexpr int A_STAGE_BYTES = BM * 128;   // 16384
constexpr int B_STAGE_BYTES = BN * 128;   // 16384
constexpr int STAGE_BYTES = A_STAGE_BYTES + B_STAGE_BYTES;   // 32768
constexpr int SMEM_TOTAL = 3 * STAGE_BYTES + 1024;           // 99328 -> 2 CTAs/SM

constexpr int THREADS = 256;              // 8 warps: 2 (M) x 4 (N), warp tile 64x32

// ---------------- device scratch (__device__ globals: allocation-free rule) ----------------
__device__ __half g_W16[(size_t)N_TOTAL * K_TOTAL];  // ternary W as fp16 (exact), 128MB
__device__ __half g_X16[(size_t)M_TOTAL * K_TOTAL];  // fp16(x), 64MB
__device__ double g_partials[2048];
__device__ float  g_scale;

// ---------------- PTX helpers ----------------
DINLINE uint32_t smem_u32(const void* p) {
    uint32_t a;
    asm("{ .reg .u64 t; cvta.to.shared.u64 t, %1; cvt.u32.u64 %0, t; }" : "=r"(a) : "l"(p));
    return a;
}

DINLINE void cp16(uint32_t dst, const void* src) {
    asm volatile("cp.async.cg.shared.global [%0], [%1], 16;"
                 :: "r"(dst), "l"(__cvta_generic_to_global(src)) : "memory");
}
#define CP_COMMIT() asm volatile("cp.async.commit_group;" ::: "memory")

DINLINE void ldsm_x4(uint32_t& r0, uint32_t& r1, uint32_t& r2, uint32_t& r3, uint32_t addr) {
    asm volatile("ldmatrix.sync.aligned.m8n8.x4.shared.b16 {%0,%1,%2,%3}, [%4];"
                 : "=r"(r0), "=r"(r1), "=r"(r2), "=r"(r3) : "r"(addr));
}

DINLINE void mma16816(float& d0, float& d1, float& d2, float& d3,
                      uint32_t a0, uint32_t a1, uint32_t a2, uint32_t a3,
                      uint32_t b0, uint32_t b1) {
    asm volatile(
        "mma.sync.aligned.m16n8k16.row.col.f32.f16.f16.f32 "
        "{%0,%1,%2,%3}, {%4,%5,%6,%7}, {%8,%9}, {%0,%1,%2,%3};"
        : "+f"(d0), "+f"(d1), "+f"(d2), "+f"(d3)
        : "r"(a0), "r"(a1), "r"(a2), "r"(a3), "r"(b0), "r"(b1));
}

// SW128 swizzle: with 128B rows, swizzled = row*128 + (col ^ ((row&7)<<4))
#define SW128(o) ((o) ^ (((o) >> 3) & 0x70))

// ---------------- prelude kernels ----------------
// Interleaved x-convert + |W| partials; compile-time trip count (exact division)
// with unroll-4 so LDGs front-batch (higher MLP -> higher DRAM utilization).
__global__ void absmean_convert(const float4* __restrict__ w, const float4* __restrict__ x) {
    constexpr int STRIDE = 2048 * 256;               // grid * block
    const int base = blockIdx.x * 256 + threadIdx.x;
    __shared__ double sh[256];
    double acc = 0.0;
#pragma unroll 4
    for (int it = 0; it < 32; it++) {                // 32 * STRIDE == WT4 exactly
        const int i = base + it * STRIDE;
        float4 v = w[i];
        acc += (double)fabsf(v.x) + (double)fabsf(v.y) + (double)fabsf(v.z) + (double)fabsf(v.w);
        if (it < 16) {                               // 16 * STRIDE == XT4 exactly (compile-time)
            float4 u = x[i];
            uint32_t h0 = (uint32_t)__half_as_ushort(__float2half_rn(u.x));
            uint32_t h1 = (uint32_t)__half_as_ushort(__float2half_rn(u.y));
            uint32_t h2 = (uint32_t)__half_as_ushort(__float2half_rn(u.z));
            uint32_t h3 = (uint32_t)__half_as_ushort(__float2half_rn(u.w));
            uint2 o;
            o.x = h0 | (h1 << 16);
            o.y = h2 | (h3 << 16);
            ((uint2*)g_X16)[i] = o;
        }
    }
    sh[threadIdx.x] = acc;
    __syncthreads();
    for (int s = 128; s > 0; s >>= 1) {
        if (threadIdx.x < s) sh[threadIdx.x] += sh[threadIdx.x + s];
        __syncthreads();
    }
    if (threadIdx.x == 0) g_partials[blockIdx.x] = sh[0];
}

__global__ void absmean_final() {
    __shared__ double sh[256];
    double a = 0.0;
    for (int i = threadIdx.x; i < 2048; i += 256) a += g_partials[i];
    sh[threadIdx.x] = a;
    __syncthreads();
    for (int s = 128; s > 0; s >>= 1) {
        if (threadIdx.x < s) sh[threadIdx.x] += sh[threadIdx.x + s];
        __syncthreads();
    }
    if (threadIdx.x == 0)
        g_scale = fmaxf((float)(sh[0] / ((double)N_TOTAL * K_TOTAL)), 1e-6f);
}

DINLINE uint32_t tern_half(float w, float s) {
    float n = w / s;  // same formula as reference
    return (fabsf(n) > 0.5f) ? ((n > 0.0f) ? 0x3C00u : 0xBC00u) : 0u;  // fp16 {+1,-1,0}
}

__global__ void quantize_w(const float4* __restrict__ w) {
    constexpr int HALF = (N_TOTAL / 4) * K_TOTAL / 2;  // 8388608
    const int base = blockIdx.x * 256 + threadIdx.x;
    const float s = g_scale;
#pragma unroll
    for (int it = 0; it < 2; it++) {                   // 2 independent streams -> MLP
        const int i = base + it * HALF;
        float4 v = w[i];
        uint2 o;
        o.x = tern_half(v.x, s) | (tern_half(v.y, s) << 16);
        o.y = tern_half(v.z, s) | (tern_half(v.w, s) << 16);
        ((uint2*)g_W16)[i] = o;
    }
}

// ---------------- main GEMM kernel: 2 CTAs/SM, unrolled-by-3 stage loop ----------------
// Mainloop structure identical to R10/R13 (best measured, tensor 87.2%).
// LC = logical chunk count (0..63); physical chunk = (LC + ch0) & 63, where ch0
// staggers alternate SM-waves by 32 chunks to de-correlate co-resident CTAs' barriers.

#define CHUNK_BODY(S, LC, LAST)                                                         \
    do {                                                                                \
        if (LAST) asm volatile("cp.async.wait_group 0;" ::: "memory");                  \
        else      asm volatile("cp.async.wait_group 1;" ::: "memory");                  \
        __syncthreads();                                                                \
        const uint32_t Abase = tiles + (S) * STAGE_BYTES;                               \
        const uint32_t Bbase = Abase + A_STAGE_BYTES;                                   \
        const uint32_t dstA  = tiles + (((S) + 2) % 3) * STAGE_BYTES + sw_off;          \
        const uint32_t dstB  = dstA + A_STAGE_BYTES;                                    \
        const int pc2 = ((LC) + 2 + ch0) & 63;                                          \
        const __half* srcA = A0 + (size_t)pc2 * BK + g_off;                             \
        const __half* srcB = B0 + (size_t)pc2 * BK + g_off;                             \
        const bool doload = ((LC) + 2 < NCHUNK);                                        \
        _Pragma("unroll")                                                               \
        for (int ks = 0; ks < 4; ks++) {                                                \
            if (doload) {                                                               \
                cp16(dstA + (ks << 12), srcA + (size_t)ks * 32 * K_TOTAL);              \
                cp16(dstB + (ks << 12), srcB + (size_t)ks * 32 * K_TOTAL);              \
            }                                                                           \
            const uint32_t kb = ks << 5;                                                \
            uint32_t bf[2][4];                                                          \
            _Pragma("unroll")                                                           \
            for (int nf2 = 0; nf2 < 2; nf2++) {                                         \
                uint32_t addr = Bbase + ((b_row + (nf2 << 4)) << 7) + ((kb + b_cadd) ^ xb); \
                ldsm_x4(bf[nf2][0], bf[nf2][1], bf[nf2][2], bf[nf2][3], addr);          \
            }                                                                           \
            uint32_t af[4][4];                                                          \
            {                                                                           \
                uint32_t addr = Abase + (a_row << 7) + ((kb + a_cadd) ^ xa);            \
                ldsm_x4(af[0][0], af[0][1], af[0][2], af[0][3], addr);                  \
            }                                                                           \
            _Pragma("unroll")                                                           \
            for (int mf = 0; mf < 4; mf++) {                                            \
                if (mf < 3) {                                                           \
                    uint32_t addr = Abase + ((a_row + ((mf + 1) << 4)) << 7)            \
                                  + ((kb + a_cadd) ^ xa);                               \
                    ldsm_x4(af[mf + 1][0], af[mf + 1][1], af[mf + 1][2], af[mf + 1][3], \
                            addr);                                                      \
                }                                                                       \
                _Pragma("unroll")                                                       \
                for (int nf = 0; nf < 4; nf++) {                                        \
                    uint32_t b0 = bf[nf >> 1][(nf & 1) << 1];                           \
                    uint32_t b1 = bf[nf >> 1][((nf & 1) << 1) + 1];                     \
                    mma16816(acc[mf][nf][0], acc[mf][nf][1],                            \
                             acc[mf][nf][2], acc[mf][nf][3],                            \
                             af[mf][0], af[mf][1], af[mf][2], af[mf][3], b0, b1);       \
                }                                                                       \
            }                                                                           \
        }                                                                               \
        CP_COMMIT();                                                                    \
    } while (0)

__global__ void __launch_bounds__(THREADS, 2) bitlinear_gemm(const float* __restrict__ bias,
                                                             float* __restrict__ out) {
    extern __shared__ char smem_raw[];
    const uint32_t tiles = (smem_u32(smem_raw) + 1023u) & ~1023u;
    const int tid = threadIdx.x;
    const int wid = tid >> 5;
    const int lid = tid & 31;

    // tile mapping with GROUP_M=16 L2 swizzle: 64 (M) x 128 (N) tiles, 8192 CTAs
    int pid = blockIdx.x;
    int grp = pid >> 11;          // / (16*128)
    int rem = pid & 2047;
    int m0 = (grp * 16 + (rem & 15)) * BM;
    int n0 = (rem >> 4) * BN;

    // K-rotation stagger: co-resident CTAs (pid, pid+148) get different phase
    const int ch0 = ((pid / 148) & 1) << 5;   // 0 or 32

    // warp layout: 2 (M) x 4 (N); warp tile 64x32
    const int warp_m0 = (wid & 1) * 64;
    const int warp_n0 = (wid >> 1) * 32;

    const __half* A0 = g_X16 + (size_t)m0 * K_TOTAL;
    const __half* B0 = g_W16 + (size_t)n0 * K_TOTAL;

    // per-thread cp.async offsets: row r = (tid>>3) + 32*ks, col byte = (tid&7)*16.
    // r+32 keeps (r&7) -> swizzled dst just advances by 32*128 = 4096 bytes per ks.
    const uint32_t sw_off = SW128((uint32_t)(((tid >> 3) << 7) | ((tid & 7) << 4)));
    const size_t   g_off  = (size_t)(tid >> 3) * K_TOTAL + (size_t)(tid & 7) * 8;

    // prologue: physical chunks ch0, ch0+1 -> stages 0, 1 (one group each; ch0+1 never wraps)
    {
        const __half* sA = A0 + (size_t)ch0 * BK + g_off;
        const __half* sB = B0 + (size_t)ch0 * BK + g_off;
#pragma unroll
        for (int ks = 0; ks < 4; ks++) {
            cp16(tiles + sw_off + (ks << 12), sA + (size_t)ks * 32 * K_TOTAL);
            cp16(tiles + A_STAGE_BYTES + sw_off + (ks << 12), sB + (size_t)ks * 32 * K_TOTAL);
        }
        CP_COMMIT();
#pragma unroll
        for (int ks = 0; ks < 4; ks++) {
            cp16(tiles + STAGE_BYTES + sw_off + (ks << 12),
                 sA + BK + (size_t)ks * 32 * K_TOTAL);
            cp16(tiles + STAGE_BYTES + A_STAGE_BYTES + sw_off + (ks << 12),
                 sB + BK + (size_t)ks * 32 * K_TOTAL);
        }
        CP_COMMIT();
    }

    // per-lane ldmatrix address components (mappings validated since R6)
    const int a_row = warp_m0 + (lid & 7) + (((lid >> 3) & 1) << 3);
    const int a_cadd = (lid >> 4) << 4;
    const uint32_t xa = (a_row & 7) << 4;
    const int b_row = warp_n0 + (lid & 7) + ((lid >> 4) << 3);
    const int b_cadd = ((lid >> 3) & 1) << 4;
    const uint32_t xb = (b_row & 7) << 4;

    float acc[4][4][4];
#pragma unroll
    for (int i = 0; i < 4; i++)
#pragma unroll
        for (int j = 0; j < 4; j++)
#pragma unroll
            for (int q = 0; q < 4; q++) acc[i][j][q] = 0.0f;

    // main loop: 21 x 3 logical chunks (0..62) with compile-time stages, then tail 63
    int lc = 0;
#pragma unroll 1
    for (int it = 0; it < 21; it++) {
        CHUNK_BODY(0, lc, false);
        CHUNK_BODY(1, lc + 1, false);
        CHUNK_BODY(2, lc + 2, false);
        lc += 3;
    }
    CHUNK_BODY(0, 63, true);

    // -------- epilogue: scale + bias --------
    const float scale = g_scale;
    const int lrow = lid >> 2;           // 0..7
    const int lcol = (lid & 3) << 1;     // 0,2,4,6
#pragma unroll
    for (int mf = 0; mf < 4; mf++) {
        const int mrow = m0 + warp_m0 + (mf << 4) + lrow;
#pragma unroll
        for (int nf = 0; nf < 4; nf++) {
            const int ncol = n0 + warp_n0 + (nf << 3) + lcol;
            const float2 b2 = *reinterpret_cast<const float2*>(bias + ncol);
            float2 v0, v1;
            v0.x = acc[mf][nf][0] * scale + b2.x;
            v0.y = acc[mf][nf][1] * scale + b2.y;
            v1.x = acc[mf][nf][2] * scale + b2.x;
            v1.y = acc[mf][nf][3] * scale + b2.y;
            *reinterpret_cast<float2*>(out + (size_t)mrow * N_TOTAL + ncol) = v0;
            *reinterpret_cast<float2*>(out + (size_t)(mrow + 8) * N_TOTAL + ncol) = v1;
        }
    }
}

// ---------------- launch ----------------
extern "C" void kernel_launch(void* const* d_in, const int* in_sizes, int n_in,
                              void* d_out, int out_size) {
    const float* x    = (const float*)d_in[0];   // [8192, 4096]
    const float* w    = (const float*)d_in[1];   // [16384, 4096]
    const float* bias = (const float*)d_in[2];   // [16384]
    float* out = (float*)d_out;                  // [8192, 16384]

    cudaFuncSetAttribute(bitlinear_gemm, cudaFuncAttributeMaxDynamicSharedMemorySize,
                         SMEM_TOTAL);

    absmean_convert<<<2048, 256>>>((const float4*)w, (const float4*)x);
    absmean_final<<<1, 256>>>();
    quantize_w<<<32768, 256>>>((const float4*)w);

    const int grid = (M_TOTAL / BM) * (N_TOTAL / BN);  // 8192
    bitlinear_gemm<<<grid, THREADS, SMEM_TOTAL>>>(bias, out);
}

// round 17
// speedup vs baseline: 1.0520x; 1.0520x over previous
#include <cuda_runtime.h>
#include <cuda_fp16.h>
#include <cstdint>

#define DINLINE __device__ __forceinline__

// ---------------- problem constants ----------------
constexpr int M_TOTAL = 8192;
constexpr int N_TOTAL = 16384;
constexpr int K_TOTAL = 4096;

// ---------------- GEMM tiling ----------------
constexpr int BM = 128;
constexpr int BN = 128;
constexpr int BK = 64;                    // fp16 elems per chunk row = 128 B (SW128 atom)
constexpr int NCHUNK = K_TOTAL / BK;      // 64
constexpr int A_STAGE_BYTES = BM * 128;   // 16384
constexpr int B_STAGE_BYTES = BN * 128;   // 16384
constexpr int STAGE_BYTES = A_STAGE_BYTES + B_STAGE_BYTES;   // 32768
constexpr int SMEM_TOTAL = 3 * STAGE_BYTES + 1024;           // 99328 -> 2 CTAs/SM

constexpr int THREADS = 256;              // 8 warps: 2 (M) x 4 (N), warp tile 64x32

// ---------------- device scratch (__device__ globals: allocation-free rule) ----------------
__device__ __half g_W16[(size_t)N_TOTAL * K_TOTAL];  // ternary W as fp16 (exact), 128MB
__device__ __half g_X16[(size_t)M_TOTAL * K_TOTAL];  // fp16(x), 64MB
__device__ double g_partials[2048];
__device__ float  g_scale;

// ---------------- PTX helpers ----------------
DINLINE uint32_t smem_u32(const void* p) {
    uint32_t a;
    asm("{ .reg .u64 t; cvta.to.shared.u64 t, %1; cvt.u32.u64 %0, t; }" : "=r"(a) : "l"(p));
    return a;
}

DINLINE void cp16(uint32_t dst, const void* src) {
    asm volatile("cp.async.cg.shared.global [%0], [%1], 16;"
                 :: "r"(dst), "l"(__cvta_generic_to_global(src)) : "memory");
}
#define CP_COMMIT() asm volatile("cp.async.commit_group;" ::: "memory")

DINLINE void ldsm_x4(uint32_t& r0, uint32_t& r1, uint32_t& r2, uint32_t& r3, uint32_t addr) {
    asm volatile("ldmatrix.sync.aligned.m8n8.x4.shared.b16 {%0,%1,%2,%3}, [%4];"
                 : "=r"(r0), "=r"(r1), "=r"(r2), "=r"(r3) : "r"(addr));
}

DINLINE void mma16816(float& d0, float& d1, float& d2, float& d3,
                      uint32_t a0, uint32_t a1, uint32_t a2, uint32_t a3,
                      uint32_t b0, uint32_t b1) {
    asm volatile(
        "mma.sync.aligned.m16n8k16.row.col.f32.f16.f16.f32 "
        "{%0,%1,%2,%3}, {%4,%5,%6,%7}, {%8,%9}, {%0,%1,%2,%3};"
        : "+f"(d0), "+f"(d1), "+f"(d2), "+f"(d3)
        : "r"(a0), "r"(a1), "r"(a2), "r"(a3), "r"(b0), "r"(b1));
}

// SW128 swizzle: with 128B rows, swizzled = row*128 + (col ^ ((row&7)<<4))
#define SW128(o) ((o) ^ (((o) >> 3) & 0x70))

// ---------------- prelude kernels (R15 version: measured ~120us) ----------------
// Interleaved x-convert + |W| partials; compile-time trip count (exact division)
// with unroll-4 so LDGs front-batch (higher MLP -> higher DRAM utilization).
__global__ void absmean_convert(const float4* __restrict__ w, const float4* __restrict__ x) {
    constexpr int STRIDE = 2048 * 256;               // grid * block
    const int base = blockIdx.x * 256 + threadIdx.x;
    __shared__ double sh[256];
    double acc = 0.0;
#pragma unroll 4
    for (int it = 0; it < 32; it++) {                // 32 * STRIDE == WT4 exactly
        const int i = base + it * STRIDE;
        float4 v = w[i];
        acc += (double)fabsf(v.x) + (double)fabsf(v.y) + (double)fabsf(v.z) + (double)fabsf(v.w);
        if (it < 16) {                               // 16 * STRIDE == XT4 exactly (compile-time)
            float4 u = x[i];
            uint32_t h0 = (uint32_t)__half_as_ushort(__float2half_rn(u.x));
            uint32_t h1 = (uint32_t)__half_as_ushort(__float2half_rn(u.y));
            uint32_t h2 = (uint32_t)__half_as_ushort(__float2half_rn(u.z));
            uint32_t h3 = (uint32_t)__half_as_ushort(__float2half_rn(u.w));
            uint2 o;
            o.x = h0 | (h1 << 16);
            o.y = h2 | (h3 << 16);
            ((uint2*)g_X16)[i] = o;
        }
    }
    sh[threadIdx.x] = acc;
    __syncthreads();
    for (int s = 128; s > 0; s >>= 1) {
        if (threadIdx.x < s) sh[threadIdx.x] += sh[threadIdx.x + s];
        __syncthreads();
    }
    if (threadIdx.x == 0) g_partials[blockIdx.x] = sh[0];
}

__global__ void absmean_final() {
    __shared__ double sh[256];
    double a = 0.0;
    for (int i = threadIdx.x; i < 2048; i += 256) a += g_partials[i];
    sh[threadIdx.x] = a;
    __syncthreads();
    for (int s = 128; s > 0; s >>= 1) {
        if (threadIdx.x < s) sh[threadIdx.x] += sh[threadIdx.x + s];
        __syncthreads();
    }
    if (threadIdx.x == 0)
        g_scale = fmaxf((float)(sh[0] / ((double)N_TOTAL * K_TOTAL)), 1e-6f);
}

DINLINE uint32_t tern_half(float w, float s) {
    float n = w / s;  // same formula as reference
    return (fabsf(n) > 0.5f) ? ((n > 0.0f) ? 0x3C00u : 0xBC00u) : 0u;  // fp16 {+1,-1,0}
}

__global__ void quantize_w(const float4* __restrict__ w) {
    constexpr int HALF = (N_TOTAL / 4) * K_TOTAL / 2;  // 8388608
    const int base = blockIdx.x * 256 + threadIdx.x;
    const float s = g_scale;
#pragma unroll
    for (int it = 0; it < 2; it++) {                   // 2 independent streams -> MLP
        const int i = base + it * HALF;
        float4 v = w[i];
        uint2 o;
        o.x = tern_half(v.x, s) | (tern_half(v.y, s) << 16);
        o.y = tern_half(v.z, s) | (tern_half(v.w, s) << 16);
        ((uint2*)g_W16)[i] = o;
    }
}

// ---------------- main GEMM kernel: exact R13 structure (best: tensor 87.2%) ----------------

#define CHUNK_BODY(S, CH, LAST)                                                         \
    do {                                                                                \
        if (LAST) asm volatile("cp.async.wait_group 0;" ::: "memory");                  \
        else      asm volatile("cp.async.wait_group 1;" ::: "memory");                  \
        __syncthreads();                                                                \
        const uint32_t Abase = tiles + (S) * STAGE_BYTES;                               \
        const uint32_t Bbase = Abase + A_STAGE_BYTES;                                   \
        const uint32_t dstA  = tiles + (((S) + 2) % 3) * STAGE_BYTES + sw_off;          \
        const uint32_t dstB  = dstA + A_STAGE_BYTES;                                    \
        const __half* srcA = A0 + (size_t)((CH) + 2) * BK + g_off;                      \
        const __half* srcB = B0 + (size_t)((CH) + 2) * BK + g_off;                      \
        const bool doload = ((CH) + 2 < NCHUNK);                                        \
        _Pragma("unroll")                                                               \
        for (int ks = 0; ks < 4; ks++) {                                                \
            if (doload) {                                                               \
                cp16(dstA + (ks << 12), srcA + (size_t)ks * 32 * K_TOTAL);              \
                cp16(dstB + (ks << 12), srcB + (size_t)ks * 32 * K_TOTAL);              \
            }                                                                           \
            const uint32_t kb = ks << 5;                                                \
            uint32_t bf[2][4];                                                          \
            _Pragma("unroll")                                                           \
            for (int nf2 = 0; nf2 < 2; nf2++) {                                         \
                uint32_t addr = Bbase + ((b_row + (nf2 << 4)) << 7) + ((kb + b_cadd) ^ xb); \
                ldsm_x4(bf[nf2][0], bf[nf2][1], bf[nf2][2], bf[nf2][3], addr);          \
            }                                                                           \
            uint32_t af[4][4];                                                          \
            {                                                                           \
                uint32_t addr = Abase + (a_row << 7) + ((kb + a_cadd) ^ xa);            \
                ldsm_x4(af[0][0], af[0][1], af[0][2], af[0][3], addr);                  \
            }                                                                           \
            _Pragma("unroll")                                                           \
            for (int mf = 0; mf < 4; mf++) {                                            \
                if (mf < 3) {                                                           \
                    uint32_t addr = Abase + ((a_row + ((mf + 1) << 4)) << 7)            \
                                  + ((kb + a_cadd) ^ xa);                               \
                    ldsm_x4(af[mf + 1][0], af[mf + 1][1], af[mf + 1][2], af[mf + 1][3], \
                            addr);                                                      \
                }                                                                       \
                _Pragma("unroll")                                                       \
                for (int nf = 0; nf < 4; nf++) {                                        \
                    uint32_t b0 = bf[nf >> 1][(nf & 1) << 1];                           \
                    uint32_t b1 = bf[nf >> 1][((nf & 1) << 1) + 1];                     \
                    mma16816(acc[mf][nf][0], acc[mf][nf][1],                            \
                             acc[mf][nf][2], acc[mf][nf][3],                            \
                             af[mf][0], af[mf][1], af[mf][2], af[mf][3], b0, b1);       \
                }                                                                       \
            }                                                                           \
        }                                                                               \
        CP_COMMIT();                                                                    \
    } while (0)

__global__ void __launch_bounds__(THREADS, 2) bitlinear_gemm(const float* __restrict__ bias,
                                                             float* __restrict__ out) {
    extern __shared__ char smem_raw[];
    const uint32_t tiles = (smem_u32(smem_raw) + 1023u) & ~1023u;
    const int tid = threadIdx.x;
    const int wid = tid >> 5;
    const int lid = tid & 31;

    // tile mapping with GROUP_M=8 L2 swizzle: 64 (M) x 128 (N) tiles, 8192 CTAs
    int pid = blockIdx.x;
    int grp = pid >> 10;         // / (8*128)
    int rem = pid & 1023;
    int m0 = (grp * 8 + (rem & 7)) * BM;
    int n0 = (rem >> 3) * BN;

    // warp layout: 2 (M) x 4 (N); warp tile 64x32
    const int warp_m0 = (wid & 1) * 64;
    const int warp_n0 = (wid >> 1) * 32;

    const __half* A0 = g_X16 + (size_t)m0 * K_TOTAL;
    const __half* B0 = g_W16 + (size_t)n0 * K_TOTAL;

    // per-thread cp.async offsets: row r = (tid>>3) + 32*ks, col byte = (tid&7)*16.
    // r+32 keeps (r&7) -> swizzled dst just advances by 32*128 = 4096 bytes per ks.
    const uint32_t sw_off = SW128((uint32_t)(((tid >> 3) << 7) | ((tid & 7) << 4)));
    const size_t   g_off  = (size_t)(tid >> 3) * K_TOTAL + (size_t)(tid & 7) * 8;

    // prologue: 2 full chunks in flight (one commit group each)
    {
        const __half* sA = A0 + g_off;
        const __half* sB = B0 + g_off;
#pragma unroll
        for (int ks = 0; ks < 4; ks++) {
            cp16(tiles + sw_off + (ks << 12), sA + (size_t)ks * 32 * K_TOTAL);
            cp16(tiles + A_STAGE_BYTES + sw_off + (ks << 12), sB + (size_t)ks * 32 * K_TOTAL);
        }
        CP_COMMIT();
#pragma unroll
        for (int ks = 0; ks < 4; ks++) {
            cp16(tiles + STAGE_BYTES + sw_off + (ks << 12),
                 sA + BK + (size_t)ks * 32 * K_TOTAL);
            cp16(tiles + STAGE_BYTES + A_STAGE_BYTES + sw_off + (ks << 12),
                 sB + BK + (size_t)ks * 32 * K_TOTAL);
        }
        CP_COMMIT();
    }

    // per-lane ldmatrix address components (mappings validated since R6)
    const int a_row = warp_m0 + (lid & 7) + (((lid >> 3) & 1) << 3);
    const int a_cadd = (lid >> 4) << 4;
    const uint32_t xa = (a_row & 7) << 4;
    const int b_row = warp_n0 + (lid & 7) + ((lid >> 4) << 3);
    const int b_cadd = ((lid >> 3) & 1) << 4;
    const uint32_t xb = (b_row & 7) << 4;

    float acc[4][4][4];
#pragma unroll
    for (int i = 0; i < 4; i++)
#pragma unroll
        for (int j = 0; j < 4; j++)
#pragma unroll
            for (int q = 0; q < 4; q++) acc[i][j][q] = 0.0f;

    // main loop: 21 x 3 chunks (0..62) with compile-time stages, then tail chunk 63
    int ch = 0;
#pragma unroll 1
    for (int it = 0; it < 21; it++) {
        CHUNK_BODY(0, ch, false);
        CHUNK_BODY(1, ch + 1, false);
        CHUNK_BODY(2, ch + 2, false);
        ch += 3;
    }
    CHUNK_BODY(0, 63, true);

    // -------- epilogue: scale + bias --------
    const float scale = g_scale;
    const int lrow = lid >> 2;           // 0..7
    const int lcol = (lid & 3) << 1;     // 0,2,4,6
#pragma unroll
    for (int mf = 0; mf < 4; mf++) {
        const int mrow = m0 + warp_m0 + (mf << 4) + lrow;
#pragma unroll
        for (int nf = 0; nf < 4; nf++) {
            const int ncol = n0 + warp_n0 + (nf << 3) + lcol;
            const float2 b2 = *reinterpret_cast<const float2*>(bias + ncol);
            float2 v0, v1;
            v0.x = acc[mf][nf][0] * scale + b2.x;
            v0.y = acc[mf][nf][1] * scale + b2.y;
            v1.x = acc[mf][nf][2] * scale + b2.x;
            v1.y = acc[mf][nf][3] * scale + b2.y;
            *reinterpret_cast<float2*>(out + (size_t)mrow * N_TOTAL + ncol) = v0;
            *reinterpret_cast<float2*>(out + (size_t)(mrow + 8) * N_TOTAL + ncol) = v1;
        }
    }
}

// ---------------- launch ----------------
extern "C" void kernel_launch(void* const* d_in, const int* in_sizes, int n_in,
                              void* d_out, int out_size) {
    const float* x    = (const float*)d_in[0];   // [8192, 4096]
    const float* w    = (const float*)d_in[1];   // [16384, 4096]
    const float* bias = (const float*)d_in[2];   // [16384]
    float* out = (float*)d_out;                  // [8192, 16384]

    cudaFuncSetAttribute(bitlinear_gemm, cudaFuncAttributeMaxDynamicSharedMemorySize,
                         SMEM_TOTAL);

    absmean_convert<<<2048, 256>>>((const float4*)w, (const float4*)x);
    absmean_final<<<1, 256>>>();
    quantize_w<<<32768, 256>>>((const float4*)w);

    const int grid = (M_TOTAL / BM) * (N_TOTAL / BN);  // 8192
    bitlinear_gemm<<<grid, THREADS, SMEM_TOTAL>>>(bias, out);
}